// round 16
// baseline (speedup 1.0000x reference)
#include <cuda_runtime.h>

#define H 512
#define W 512
#define MASK 511
#define NPLANE (H * W)
#define NTH 256
#define NBLK 128                 // <= 148 SMs: all co-resident in wave 1

#define FSTRIDE 580              // float2 stride per sub-FFT region
#define PAD(i) ((i) + ((i) >> 3))

__device__ float2 g_T[NPLANE];   // row spectra, transposed: g_T[kj*512 + r]
__device__ float2 g_Z[NPLANE];   // Z_hat, row-major:        g_Z[ki*512 + kj]

// ---------------------------------------------------- two-hop grid barrier
// (proven: block 0 aggregates flags, single release word broadcast;
//  monotonic counters -> safe across graph replays)
__device__ volatile unsigned g_flag[2][NBLK];
__device__ volatile unsigned g_rel[2];

__device__ __forceinline__ void bar_arrive(int n, int tid, int blk, const unsigned* fb) {
    __syncthreads();             // all phase work in this block done
    __threadfence();             // make its stores globally visible
    if (tid == 0) g_flag[n][blk] = fb[n];
}
__device__ __forceinline__ void bar_wait(int n, int tid, int blk,
                                         const unsigned* rb, const unsigned* ft) {
    if (blk == 0) {
        if (tid < NBLK) { while (g_flag[n][tid] < ft[n]) { } }
        __syncthreads();
        __threadfence();
        if (tid == 0) g_rel[n] = rb[n];
    } else {
        if (tid == 0) {
            while (g_rel[n] < rb[n]) { }
            __threadfence();
        }
        __syncthreads();
    }
}

// ------------------------------------------------------------- complex ops
__device__ __forceinline__ float2 cmul(float2 a, float2 b) {
    return make_float2(a.x * b.x - a.y * b.y, a.x * b.y + a.y * b.x);
}
__device__ __forceinline__ float2 cadd(float2 a, float2 b) { return make_float2(a.x + b.x, a.y + b.y); }
__device__ __forceinline__ float2 csub(float2 a, float2 b) { return make_float2(a.x - b.x, a.y - b.y); }

// partial component c at (i,j), computed directly from X, F.
__device__ __forceinline__ float partial_c(const float* __restrict__ X,
                                           const float* __restrict__ F,
                                           int c, int i, int j) {
    int im = (i - 1) & MASK, ip = (i + 1) & MASK;
    int jm = (j - 1) & MASK, jp = (j + 1) & MASK;
    int id = i * W + j;
    const float* xc = X + c * NPLANE;
    float ctr = xc[id];
    float up = xc[im * W + j];
    float dn = xc[ip * W + j];
    float lf = xc[i * W + jm];
    float rt = xc[i * W + jp];
    float u = X[id];
    float v = X[NPLANE + id];
    float dx = (dn - up) * 0.5f;
    float dy = (rt - lf) * 0.5f;
    float lap = (up + dn + lf + rt) - 4.0f * ctr;
    return -(u * dx + v * dy) + 0.1f * lap + F[c * NPLANE + id];
}

// 8-point DFT, natural order, constant twiddles. SIGN=-1 forward.
template <int SIGN>
__device__ __forceinline__ void dft8(const float2* a, float2* y) {
    const float C = 0.70710678118654752f;
    const float S = (float)SIGN;
    float2 u[8], v[8];
#pragma unroll
    for (int p = 0; p < 4; ++p) {
        float2 A = a[p], B = a[p + 4];
        float2 d = csub(A, B);
        u[2 * p] = cadd(A, B);
        float2 w = (p == 0) ? make_float2(1.f, 0.f)
                 : (p == 1) ? make_float2(C, S * C)
                 : (p == 2) ? make_float2(0.f, S)
                            : make_float2(-C, S * C);
        u[2 * p + 1] = cmul(d, w);
    }
#pragma unroll
    for (int tt = 0; tt < 4; ++tt) {
        int p = tt >> 1, q = tt & 1;
        float2 A = u[q + 2 * p], B = u[q + 2 * p + 4];
        float2 d = csub(A, B);
        v[q + 4 * p] = cadd(A, B);
        v[q + 4 * p + 2] = (p == 0) ? d : cmul(d, make_float2(0.f, S));
    }
#pragma unroll
    for (int q = 0; q < 4; ++q) {
        float2 A = v[q], B = v[q + 4];
        y[q] = cadd(A, B);
        y[q + 4] = csub(A, B);
    }
}

// 512-pt radix-8 Stockham FFT; 64 threads/FFT, 8 elems in registers.
// x[e] holds element (t + 64e) in, bin (t + 64e) out. 2 syncthreads.
template <int SIGN>
__device__ __forceinline__ void fft512_r8(float2* x, float2* sA, float2* sB, int t) {
    float2 y[8];
    dft8<SIGN>(x, y);
    {
        float base = (float)SIGN * 0.012271846303085130f * (float)t;   // 2π/512·t
#pragma unroll
        for (int e = 1; e < 8; ++e) {
            float sn, cs;
            __sincosf(base * (float)e, &sn, &cs);
            y[e] = cmul(y[e], make_float2(cs, sn));
        }
#pragma unroll
        for (int e = 0; e < 8; ++e) sA[PAD(8 * t + e)] = y[e];
    }
    __syncthreads();
#pragma unroll
    for (int e = 0; e < 8; ++e) x[e] = sA[PAD(t + 64 * e)];
    dft8<SIGN>(x, y);
    {
        int p = t >> 3, q = t & 7;
        float base = (float)SIGN * 0.098174770424681f * (float)p;      // 2π/64·p
#pragma unroll
        for (int e = 1; e < 8; ++e) {
            float sn, cs;
            __sincosf(base * (float)e, &sn, &cs);
            y[e] = cmul(y[e], make_float2(cs, sn));
        }
        int wb = 8 * t - 7 * q;
#pragma unroll
        for (int e = 0; e < 8; ++e) sB[PAD(wb + 8 * e)] = y[e];
    }
    __syncthreads();
#pragma unroll
    for (int e = 0; e < 8; ++e) x[e] = sB[PAD(t + 64 * e)];
    dft8<SIGN>(x, y);
#pragma unroll
    for (int e = 0; e < 8; ++e) x[e] = y[e];
}

// Multiplier M = T(ki,kj)/N^2 · (−sy + i·sx), where T is the transfer
// function of 1000 Jacobi iterations with phi0 = B (accurate path).
__device__ __forceinline__ float2 jacobi_M(int ki, int kj) {
    const float invN2 = 1.0f / 262144.0f;
    float sx = __sinf(0.012271846303085130f * (float)ki);   // sin(2π ki/512)
    float sy = __sinf(0.012271846303085130f * (float)kj);
    float sa = sinf(0.0061359231515f * (float)ki);          // sin(π ki/512)
    float sb = sinf(0.0061359231515f * (float)kj);
    float oms = sa * sa + sb * sb;                          // 1 - s (no cancellation)
    float T;
    if (oms <= 0.0f) {
        T = -249.0f * invN2;                                // ki=kj=0
    } else {
        float arg = 500.0f * log1pf(-oms * (2.0f - oms));   // log(s^1000)
        float s1000 = (arg < -87.0f) ? 0.0f : expf(arg);
        T = (s1000 - (1.0f - s1000) / (4.0f * oms)) * invN2;
    }
    return make_float2(-T * sy, T * sx);
}

// ------------------------------------------------------------- fused kernel
__global__ void __launch_bounds__(NTH) k_fused(const float* __restrict__ X,
                                               const float* __restrict__ F,
                                               float* __restrict__ out) {
    __shared__ float2 sm[2 * 4 * FSTRIDE];
    const int tid = threadIdx.x;
    const int blk = blockIdx.x;

    // barrier bookkeeping (monotonic counters; replay-safe)
    unsigned fb[2] = {0, 0}, rb[2] = {0, 0}, ft[2] = {0, 0};
    if (tid == 0) {
        fb[0] = g_flag[0][blk] + 1;  fb[1] = g_flag[1][blk] + 1;
        rb[0] = g_rel[0] + 1;        rb[1] = g_rel[1] + 1;
    }
    if (blk == 0 && tid < NBLK) {
        ft[0] = g_flag[0][tid] + 1;  ft[1] = g_flag[1][tid] + 1;
    }

    // ================= Phase A: B inline + fwd row FFT, direct transposed store
    {
        int f = tid >> 6, t = tid & 63;
        int r = blk * 4 + f;
        float2* sA = sm + f * FSTRIDE;
        float2* sB = sm + (4 + f) * FSTRIDE;
        int rp = (r + 1) & MASK, rm = (r - 1) & MASK;

        float2 x[8];
#pragma unroll
        for (int e = 0; e < 8; ++e) {
            int j = t + 64 * e;
            int jp = (j + 1) & MASK, jm = (j - 1) & MASK;
            float b = ((partial_c(X, F, 0, rp, j) - partial_c(X, F, 0, rm, j))
                     + (partial_c(X, F, 1, r, jp) - partial_c(X, F, 1, r, jm))) * 5.0f;
            x[e] = make_float2(b, 0.0f);
        }
        fft512_r8<-1>(x, sA, sB, t);
#pragma unroll
        for (int e = 0; e < 8; ++e) g_T[(t + 64 * e) * W + r] = x[e];
    }
    bar_arrive(0, tid, blk, fb);

    // ---- phase-B prologue (index-only): spectral multiplier, overlaps barrier
    int fB = tid & 3, tB = tid >> 2;
    int c = blk * 4 + fB;                       // kj
    float2 m[8];
#pragma unroll
    for (int e = 0; e < 8; ++e) m[e] = jacobi_M(tB + 64 * e, c);
    bar_wait(0, tid, blk, rb, ft);

    // ================= Phase B: col fwd FFT, multiply, col inv FFT
    {
        float2* sA = sm + fB * FSTRIDE;
        float2* sB = sm + (4 + fB) * FSTRIDE;

        float2 x[8];
#pragma unroll
        for (int e = 0; e < 8; ++e) x[e] = g_T[c * W + tB + 64 * e];   // coalesced
        fft512_r8<-1>(x, sA, sB, tB);
#pragma unroll
        for (int e = 0; e < 8; ++e) x[e] = cmul(x[e], m[e]);
        fft512_r8<1>(x, sA, sB, tB);
#pragma unroll
        for (int e = 0; e < 8; ++e) g_Z[(tB + 64 * e) * W + c] = x[e]; // scattered stores
    }
    bar_arrive(1, tid, blk, fb);

    // ---- phase-C prologue (reads only X,F): partial recompute, overlaps barrier
    int fC = tid >> 6, tC = tid & 63;
    int r = blk * 4 + fC;
    float p0[8], p1[8];
#pragma unroll
    for (int e = 0; e < 8; ++e) {
        int j = tC + 64 * e;
        p0[e] = partial_c(X, F, 0, r, j);
        p1[e] = partial_c(X, F, 1, r, j);
    }
    bar_wait(1, tid, blk, rb, ft);

    // ================= Phase C: inverse row FFT + epilogue
    {
        float2* sA = sm + fC * FSTRIDE;
        float2* sB = sm + (4 + fC) * FSTRIDE;

        float2 x[8];
#pragma unroll
        for (int e = 0; e < 8; ++e) x[e] = g_Z[r * W + tC + 64 * e];   // coalesced
        fft512_r8<1>(x, sA, sB, tC);
#pragma unroll
        for (int e = 0; e < 8; ++e) {
            int id = r * W + tC + 64 * e;
            out[id]          = p0[e] - x[e].x;    // gx = Re
            out[NPLANE + id] = p1[e] - x[e].y;    // gy = Im
        }
    }
}

extern "C" void kernel_launch(void* const* d_in, const int* in_sizes, int n_in,
                              void* d_out, int out_size) {
    const float* X = (const float*)d_in[1];
    const float* F = (const float*)d_in[2];
    float* out = (float*)d_out;
    k_fused<<<NBLK, NTH>>>(X, F, out);
}

// round 17
// speedup vs baseline: 1.4349x; 1.4349x over previous
#include <cuda_runtime.h>

#define H 512
#define W 512
#define MASK 511
#define NPLANE (H * W)
#define NTH 256

#define FSTRIDE 580              // float2 stride per sub-FFT (bank-offset 8f)
#define PAD(i) ((i) + ((i) >> 3))

__device__ float  g_partial[2 * NPLANE];
__device__ float2 g_Fhat[NPLANE];

__device__ __forceinline__ float2 cmul(float2 a, float2 b) {
    return make_float2(a.x * b.x - a.y * b.y, a.x * b.y + a.y * b.x);
}
__device__ __forceinline__ float2 cadd(float2 a, float2 b) { return make_float2(a.x + b.x, a.y + b.y); }
__device__ __forceinline__ float2 csub(float2 a, float2 b) { return make_float2(a.x - b.x, a.y - b.y); }

// 8-point DFT, natural order in/out, constant twiddles. SIGN=-1 forward.
template <int SIGN>
__device__ __forceinline__ void dft8(const float2* a, float2* y) {
    const float C = 0.70710678118654752f;
    const float S = (float)SIGN;
    float2 u[8], v[8];
#pragma unroll
    for (int p = 0; p < 4; ++p) {          // s=1, n=8
        float2 A = a[p], B = a[p + 4];
        float2 d = csub(A, B);
        u[2 * p] = cadd(A, B);
        float2 w = (p == 0) ? make_float2(1.f, 0.f)
                 : (p == 1) ? make_float2(C, S * C)
                 : (p == 2) ? make_float2(0.f, S)
                            : make_float2(-C, S * C);
        u[2 * p + 1] = cmul(d, w);
    }
#pragma unroll
    for (int tt = 0; tt < 4; ++tt) {       // s=2, n=4
        int p = tt >> 1, q = tt & 1;
        float2 A = u[q + 2 * p], B = u[q + 2 * p + 4];
        float2 d = csub(A, B);
        v[q + 4 * p] = cadd(A, B);
        v[q + 4 * p + 2] = (p == 0) ? d : cmul(d, make_float2(0.f, S));
    }
#pragma unroll
    for (int q = 0; q < 4; ++q) {          // s=4, n=2
        float2 A = v[q], B = v[q + 4];
        y[q] = cadd(A, B);
        y[q + 4] = csub(A, B);
    }
}

// 512-pt radix-8 Stockham FFT; 64 threads per FFT, 8 elems/thread.
// In/out in registers: x[e] = element (t + 64e); output x[e] = bin (t + 64e).
// 2 __syncthreads per call.
template <int SIGN>
__device__ __forceinline__ void fft512_r8(float2* x, float2* sA, float2* sB, int t) {
    float2 y[8];
    // stage 0: s=1, n=512, p=t, q=0
    dft8<SIGN>(x, y);
    {
        float base = (float)SIGN * 0.012271846303085130f * (float)t;  // 2π/512 * t
#pragma unroll
        for (int e = 1; e < 8; ++e) {
            float sn, cs;
            __sincosf(base * (float)e, &sn, &cs);
            y[e] = cmul(y[e], make_float2(cs, sn));
        }
#pragma unroll
        for (int e = 0; e < 8; ++e) sA[PAD(8 * t + e)] = y[e];
    }
    __syncthreads();
    // stage 1: s=8, n=64, p=t>>3, q=t&7
#pragma unroll
    for (int e = 0; e < 8; ++e) x[e] = sA[PAD(t + 64 * e)];
    dft8<SIGN>(x, y);
    {
        int p = t >> 3, q = t & 7;
        float base = (float)SIGN * 0.098174770424681f * (float)p;      // 2π/64 * p
#pragma unroll
        for (int e = 1; e < 8; ++e) {
            float sn, cs;
            __sincosf(base * (float)e, &sn, &cs);
            y[e] = cmul(y[e], make_float2(cs, sn));
        }
        int wb = 8 * t - 7 * q;
#pragma unroll
        for (int e = 0; e < 8; ++e) sB[PAD(wb + 8 * e)] = y[e];
    }
    __syncthreads();
    // stage 2: s=64, p=0, q=t — no twiddle; output in natural order at (t+64e)
#pragma unroll
    for (int e = 0; e < 8; ++e) x[e] = sB[PAD(t + 64 * e)];
    dft8<SIGN>(x, y);
#pragma unroll
    for (int e = 0; e < 8; ++e) x[e] = y[e];
}

// Transfer function of 1000 Jacobi iterations (phi0 = B), incl. 1/N^2.
__device__ __forceinline__ float jacobi_T(int ki, int kj) {
    const float invN2 = 1.0f / 262144.0f;
    float sa = sinf(0.0061359231515f * (float)ki);   // sin(pi*ki/512)
    float sb = sinf(0.0061359231515f * (float)kj);
    float oms = sa * sa + sb * sb;                   // 1 - s, no cancellation
    if (oms <= 0.0f) return -249.0f * invN2;
    float arg = 500.0f * log1pf(-oms * (2.0f - oms));  // log(s^1000)
    float s1000 = (arg < -87.0f) ? 0.0f : expf(arg);
    return (s1000 - (1.0f - s1000) / (4.0f * oms)) * invN2;
}

// ---------------------------------------------------------------- kernels
__global__ void k_partial(const float* __restrict__ X, const float* __restrict__ F) {
    int id = blockIdx.x * blockDim.x + threadIdx.x;
    if (id >= NPLANE) return;
    int i = id >> 9, j = id & MASK;
    int im = (i - 1) & MASK, ip = (i + 1) & MASK;
    int jm = (j - 1) & MASK, jp = (j + 1) & MASK;

    float u = X[id];
    float v = X[NPLANE + id];
    const float NU = 0.1f;
#pragma unroll
    for (int c = 0; c < 2; ++c) {
        const float* xc = X + c * NPLANE;
        float ctr = xc[id];
        float up = xc[im * W + j];
        float dn = xc[ip * W + j];
        float lf = xc[i * W + jm];
        float rt = xc[i * W + jp];
        float dx = (dn - up) * 0.5f;
        float dy = (rt - lf) * 0.5f;
        float lap = (up + dn + lf + rt) - 4.0f * ctr;
        g_partial[c * NPLANE + id] = -(u * dx + v * dy) + NU * lap + F[c * NPLANE + id];
    }
}

// Rows forward: compute B inline from g_partial, FFT along j -> g_Fhat.
__global__ void __launch_bounds__(NTH) k_rows_fwd() {
    __shared__ float2 sm[2 * 4 * FSTRIDE];
    int f = threadIdx.x >> 6, t = threadIdx.x & 63;
    int r = blockIdx.x * 4 + f;
    float2* sA = sm + f * FSTRIDE;
    float2* sB = sm + (4 + f) * FSTRIDE;
    const float* p0 = g_partial;
    const float* p1 = g_partial + NPLANE;
    int rp = (r + 1) & MASK, rm = (r - 1) & MASK;

    float2 x[8];
#pragma unroll
    for (int e = 0; e < 8; ++e) {
        int j = t + 64 * e;
        int jp = (j + 1) & MASK, jm = (j - 1) & MASK;
        // RHO/(2*DX*DT) = 5
        float b = ((p0[rp * W + j] - p0[rm * W + j]) + (p1[r * W + jp] - p1[r * W + jm])) * 5.0f;
        x[e] = make_float2(b, 0.0f);
    }
    fft512_r8<-1>(x, sA, sB, t);
#pragma unroll
    for (int e = 0; e < 8; ++e) g_Fhat[r * W + t + 64 * e] = x[e];
}

// Columns: fwd FFT along i, multiply by T*(−sy + i*sx)/N^2, inverse FFT along i.
__global__ void __launch_bounds__(NTH) k_cols() {
    __shared__ float2 sm[2 * 4 * FSTRIDE];
    int f = threadIdx.x & 3, t = threadIdx.x >> 2;
    int c = blockIdx.x * 4 + f;
    float2* sA = sm + f * FSTRIDE;
    float2* sB = sm + (4 + f) * FSTRIDE;

    float2 x[8];
#pragma unroll
    for (int e = 0; e < 8; ++e) x[e] = g_Fhat[(t + 64 * e) * W + c];
    fft512_r8<-1>(x, sA, sB, t);

    float sy = __sinf(0.012271846303085130f * (float)c);   // sin(2π kj/512)
#pragma unroll
    for (int e = 0; e < 8; ++e) {
        int ki = t + 64 * e;
        float Tv = jacobi_T(ki, c);
        float sx = __sinf(0.012271846303085130f * (float)ki);
        x[e] = cmul(x[e], make_float2(-Tv * sy, Tv * sx));  // Zhat = phi_hat*(i*sx - sy)
    }
    fft512_r8<1>(x, sA, sB, t);
#pragma unroll
    for (int e = 0; e < 8; ++e) g_Fhat[(t + 64 * e) * W + c] = x[e];
}

// Rows inverse + epilogue: Z = gx + i*gy ; out[c] = partial[c] - (Re,Im)Z.
__global__ void __launch_bounds__(NTH) k_rows_inv_out(float* __restrict__ out) {
    __shared__ float2 sm[2 * 4 * FSTRIDE];
    int f = threadIdx.x >> 6, t = threadIdx.x & 63;
    int r = blockIdx.x * 4 + f;
    float2* sA = sm + f * FSTRIDE;
    float2* sB = sm + (4 + f) * FSTRIDE;

    float2 x[8];
#pragma unroll
    for (int e = 0; e < 8; ++e) x[e] = g_Fhat[r * W + t + 64 * e];
    fft512_r8<1>(x, sA, sB, t);
#pragma unroll
    for (int e = 0; e < 8; ++e) {
        int id = r * W + t + 64 * e;
        out[id]          = g_partial[id]          - x[e].x;
        out[NPLANE + id] = g_partial[NPLANE + id] - x[e].y;
    }
}

extern "C" void kernel_launch(void* const* d_in, const int* in_sizes, int n_in,
                              void* d_out, int out_size) {
    const float* X = (const float*)d_in[1];
    const float* F = (const float*)d_in[2];
    float* out = (float*)d_out;

    k_partial<<<NPLANE / NTH, NTH>>>(X, F);
    k_rows_fwd<<<H / 4, NTH>>>();
    k_cols<<<W / 4, NTH>>>();
    k_rows_inv_out<<<H / 4, NTH>>>(out);
}